// round 14
// baseline (speedup 1.0000x reference)
#include <cuda_runtime.h>
#include <cuda_fp16.h>

#define Bb 8
#define Hh 9
#define Ee 128
#define Ss 1025
#define SPAD 1152   // padded sequence (rows/cols >=1025 stay zero-initialized)
#define HE 1152
#define ROWP 8320   // padded out-proj row count (65*128)
#define CP 40       // fp16 pitch for [128 x 32] k-chunk tiles
#define CTILE 10240 // 128*40*2 bytes
#define VP 136      // fp16 pitch for [32 x 128] B-trans chunk tiles
#define VTILE32 8704 // 32*136*2 bytes
#define OAP 72      // outproj pitch for k64 tiles
#define OATILE 9216  // 64*72*2
#define OBTILE 18432 // 128*72*2
#define QP2 136      // resident q pitch (full-K tiles)
#define QTILEF 34816 // 128*136*2 bytes

typedef unsigned long long ull;
typedef unsigned int u32;

// ---------------- scratch (zero-initialized BSS; padding never written) ------
__device__ __half g_x0[Bb * SPAD * 128], g_x1[Bb * SPAD * 128];
__device__ __half g_wq0[Hh * Ee * Ee], g_wq1[Hh * Ee * Ee];
__device__ __half g_wk0[Hh * Ee * Ee], g_wk1[Hh * Ee * Ee];
__device__ __half g_wv0[Hh * Ee * Ee], g_wv1[Hh * Ee * Ee];
__device__ __half g_q0[72 * SPAD * 128], g_q1[72 * SPAD * 128];
__device__ __half g_k0[72 * SPAD * 128], g_k1[72 * SPAD * 128];
__device__ __half g_v0[72 * SPAD * 128];
__device__ __half g_p0[(size_t)72 * SPAD * SPAD];
__device__ __half g_h0[ROWP * HE];
__device__ __half g_w0[Ee * HE];

// ---------------- async copy / mma helpers ----------------
__device__ __forceinline__ u32 s2u(const void* p) {
    u32 a;
    asm("{ .reg .u64 t; cvta.to.shared.u64 t, %1; cvt.u32.u64 %0, t; }" : "=r"(a) : "l"(p));
    return a;
}
__device__ __forceinline__ void cp16(u32 smem, const void* g) {
    asm volatile("cp.async.cg.shared.global [%0], [%1], 16;" :: "r"(smem), "l"(g));
}
__device__ __forceinline__ void cp_commit() { asm volatile("cp.async.commit_group;" ::: "memory"); }
template <int N> __device__ __forceinline__ void cp_wait() {
    asm volatile("cp.async.wait_group %0;" :: "n"(N) : "memory");
}
__device__ __forceinline__ void ldmx4(u32& a0, u32& a1, u32& a2, u32& a3, u32 addr) {
    asm volatile("ldmatrix.sync.aligned.m8n8.x4.shared.b16 {%0,%1,%2,%3}, [%4];"
                 : "=r"(a0), "=r"(a1), "=r"(a2), "=r"(a3) : "r"(addr));
}
__device__ __forceinline__ void ldmx2(u32& b0, u32& b1, u32 addr) {
    asm volatile("ldmatrix.sync.aligned.m8n8.x2.shared.b16 {%0,%1}, [%2];"
                 : "=r"(b0), "=r"(b1) : "r"(addr));
}
__device__ __forceinline__ void ldmx2t(u32& b0, u32& b1, u32 addr) {
    asm volatile("ldmatrix.sync.aligned.m8n8.x2.trans.shared.b16 {%0,%1}, [%2];"
                 : "=r"(b0), "=r"(b1) : "r"(addr));
}
__device__ __forceinline__ void mma16816(float* c, u32 a0, u32 a1, u32 a2, u32 a3,
                                         u32 b0, u32 b1) {
    asm volatile("mma.sync.aligned.m16n8k16.row.col.f32.f16.f16.f32 "
                 "{%0,%1,%2,%3}, {%4,%5,%6,%7}, {%8,%9}, {%0,%1,%2,%3};"
                 : "+f"(c[0]), "+f"(c[1]), "+f"(c[2]), "+f"(c[3])
                 : "r"(a0), "r"(a1), "r"(a2), "r"(a3), "r"(b0), "r"(b1));
}
__device__ __forceinline__ void hsplit2(float x, __half& a, __half& b) {
    a = __float2half_rn(x);
    b = __float2half_rn(x - __half2float(a));
}

// =================================================================
// Kernel 0a: W -> fp16 (single level)
// =================================================================
__global__ __launch_bounds__(256) void wprep_kernel(const float* __restrict__ Wm)
{
    int idx = blockIdx.x * 256 + threadIdx.x;
    if (idx < Ee * HE)
        g_w0[idx] = __float2half_rn(Wm[idx]);
}

// =================================================================
// Kernel 0b: split Q/K/V weight matrices into fp16 levels
// =================================================================
__global__ __launch_bounds__(256) void qkvprep_kernel(
    const float* __restrict__ Qw, const float* __restrict__ Kw,
    const float* __restrict__ Vw)
{
    int idx = blockIdx.x * 256 + threadIdx.x;
    const int N = Hh * Ee * Ee;
    if (idx < 3 * N) {
        int z = idx / N, j = idx % N;
        const float* src = (z == 0) ? Qw : (z == 1) ? Kw : Vw;
        __half* d0 = (z == 0) ? g_wq0 : (z == 1) ? g_wk0 : g_wv0;
        __half* d1 = (z == 0) ? g_wq1 : (z == 1) ? g_wk1 : g_wv1;
        __half a, b;
        hsplit2(src[j], a, b);
        d0[j] = a;
        d1[j] = b;
    }
}

// =================================================================
// Kernel 0c: transpose x [B,E,S] -> xt splits [b][s][e] fp16 x2
// =================================================================
__global__ __launch_bounds__(256) void xprep_kernel(const float* __restrict__ x)
{
    __shared__ float ts[128 * 65];
    const int tid = threadIdx.x;
    const int s0 = blockIdx.x * 64;
    const int b = blockIdx.y;

    #pragma unroll
    for (int it = 0; it < 32; ++it) {
        int idx = tid + it * 256;
        int e = idx >> 6, sl = idx & 63;
        int s = s0 + sl;
        ts[e * 65 + sl] = (s < Ss) ? x[((size_t)b * Ee + e) * Ss + s] : 0.f;
    }
    __syncthreads();
    #pragma unroll
    for (int it = 0; it < 32; ++it) {
        int idx = tid + it * 256;
        int sl = idx >> 7, e = idx & 127;
        int s = s0 + sl;
        if (s < Ss) {
            __half a, bb;
            hsplit2(ts[e * 65 + sl], a, bb);
            size_t o = ((size_t)b * SPAD + s) * 128 + e;
            g_x0[o] = a;
            g_x1[o] = bb;
        }
    }
}

// =================================================================
// Kernel 1: projections via fp16 HMMA (3 products), 4 k32 chunks.
// Grid (9, 8, 27). 2 CTAs/SM. q/k get split2 output; v single fp16.
// =================================================================
__global__ __launch_bounds__(256, 2) void proj_kernel()
{
    extern __shared__ __align__(16) unsigned char sm[];
    const u32 sbase = s2u(sm);
    const int tid = threadIdx.x, wid = tid >> 5, lane = tid & 31;
    const int m0 = blockIdx.x * 128;
    const int b = blockIdx.y;
    const int zt = blockIdx.z % 3, h = blockIdx.z / 3;
    const int wr = wid >> 2, wc = wid & 3;
    const int l15 = lane & 15;
    const int STG = 2 * CTILE + 2 * VTILE32;   // 37,888

    const __half* w0 = (zt == 0) ? g_wq0 : (zt == 1) ? g_wk0 : g_wv0;
    const __half* w1 = (zt == 0) ? g_wq1 : (zt == 1) ? g_wk1 : g_wv1;

    auto load_chunk = [&](int st, int ck) {
        const int e0 = ck * 32;
        for (int i = tid; i < 2048; i += 256) {
            if (i < 1024) {
                int t = i >> 9, rc = i & 511, r = rc >> 2, c = rc & 3;
                const __half* g = (t ? g_x1 : g_x0) +
                    ((size_t)b * SPAD + m0 + r) * 128 + e0 + c * 8;
                cp16(sbase + st * STG + t * CTILE + (r * CP + c * 8) * 2, g);
            } else {
                int j = i - 1024;
                int t = j >> 9, rc = j & 511, r = rc >> 4, c = rc & 15;
                const __half* g = (t ? w1 : w0) + ((size_t)h * 128 + e0 + r) * 128 + c * 8;
                cp16(sbase + st * STG + 2 * CTILE + t * VTILE32 + (r * VP + c * 8) * 2, g);
            }
        }
        cp_commit();
    };

    float acc[4][4][4];
    #pragma unroll
    for (int mt = 0; mt < 4; ++mt)
        #pragma unroll
        for (int nt = 0; nt < 4; ++nt)
            #pragma unroll
            for (int i = 0; i < 4; ++i) acc[mt][nt][i] = 0.f;

    load_chunk(0, 0);
    for (int ck = 0; ck < 4; ++ck) {
        if (ck + 1 < 4) load_chunk((ck + 1) & 1, ck + 1);
        if (ck + 1 < 4) cp_wait<1>(); else cp_wait<0>();
        __syncthreads();

        const u32 st = sbase + (ck & 1) * STG;
        const int PA[3] = {0, 0, 1};
        const int PB[3] = {0, 1, 0};
        #pragma unroll
        for (int l = 0; l < 3; ++l) {
            u32 abase = st + PA[l] * CTILE;
            u32 vbase = st + 2 * CTILE + PB[l] * VTILE32;
            #pragma unroll
            for (int k = 0; k < 2; ++k) {
                const int k0 = k * 16;
                u32 bfrag[4][2];
                u32 brow = vbase + ((k0 + l15) * VP) * 2;
                #pragma unroll
                for (int nt = 0; nt < 4; ++nt)
                    ldmx2t(bfrag[nt][0], bfrag[nt][1], brow + (wc * 32 + nt * 8) * 2);
                u32 arow = abase + ((wr * 64 + l15) * CP + k0 + ((lane >> 4) * 8)) * 2;
                #pragma unroll
                for (int mt = 0; mt < 4; ++mt) {
                    u32 a0, a1, a2, a3;
                    ldmx4(a0, a1, a2, a3, arow + (mt * 16 * CP) * 2);
                    #pragma unroll
                    for (int nt = 0; nt < 4; ++nt)
                        mma16816(acc[mt][nt], a0, a1, a2, a3, bfrag[nt][0], bfrag[nt][1]);
                }
            }
        }
        __syncthreads();
    }

    // epilogue: regs -> stage -> q/k fp16 splits (v: single level)
    float* stage = (float*)sm;   // [128][130]
    {
        int row = wr * 64 + (lane >> 2);
        int col = wc * 32 + (lane & 3) * 2;
        #pragma unroll
        for (int mt = 0; mt < 4; ++mt)
            #pragma unroll
            for (int nt = 0; nt < 4; ++nt) {
                float* c = acc[mt][nt];
                int rr = row + mt * 16, cc = col + nt * 8;
                *(float2*)&stage[rr * 130 + cc]       = make_float2(c[0], c[1]);
                *(float2*)&stage[(rr + 8) * 130 + cc] = make_float2(c[2], c[3]);
            }
    }
    __syncthreads();
    __half* d0 = (zt == 0) ? g_q0 : (zt == 1) ? g_k0 : g_v0;
    __half* d1 = (zt == 0) ? g_q1 : g_k1;   // valid only when zt < 2
    const int bh = b * Hh + h;
    for (int idx = tid; idx < 128 * 16; idx += 256) {
        int rr = idx >> 4, c8 = (idx & 15) * 8;
        int s = m0 + rr;
        if (s < Ss) {
            size_t base = ((size_t)bh * SPAD + s) * 128 + c8;
            union { uint4 u; __half hh[8]; } h0, h1;
            if (zt < 2) {
                #pragma unroll
                for (int c = 0; c < 8; ++c)
                    hsplit2(stage[rr * 130 + c8 + c], h0.hh[c], h1.hh[c]);
                *(uint4*)&d0[base] = h0.u;
                *(uint4*)&d1[base] = h1.u;
            } else {
                #pragma unroll
                for (int c = 0; c < 8; ++c)
                    h0.hh[c] = __float2half_rn(stage[rr * 130 + c8 + c]);
                *(uint4*)&d0[base] = h0.u;
            }
        }
    }
}

// =================================================================
// Kernel 2: scores, q-resident. Grid (9, 72). 2 CTAs/SM.
// smem: q0|q1 full-K [128][QP2] (69,632) + 2-stage k chunks (2*2*CTILE=40,960)
// n-tiles 0..7 only (col 1024 handled by lastcol_kernel).
// =================================================================
__global__ __launch_bounds__(256, 2) void scores_kernel(float* __restrict__ atten)
{
    extern __shared__ __align__(16) unsigned char sm[];
    const u32 sbase = s2u(sm);
    const int tid = threadIdx.x, wid = tid >> 5, lane = tid & 31;
    const int m0 = blockIdx.x * 128;
    const int bh = blockIdx.y;
    const int wr = wid >> 2, wc = wid & 3;
    const int l15 = lane & 15;
    const u32 kbase = sbase + 2 * QTILEF;
    const int KSTG = 2 * CTILE;   // 20,480

    // resident q0/q1 (full K=128): 2 levels x 128 rows x 16 col-groups of 8
    for (int i = tid; i < 4096; i += 256) {
        int lvl = i >> 11, rc = i & 2047, r = rc >> 4, c = rc & 15;
        const __half* g = (lvl ? g_q1 : g_q0) + ((size_t)bh * SPAD + m0 + r) * 128 + c * 8;
        cp16(sbase + lvl * QTILEF + (r * QP2 + c * 8) * 2, g);
    }
    cp_commit();

    auto load_k = [&](int st, int cc) {
        const int n0 = (cc >> 2) * 128, e0 = (cc & 3) * 32;
        for (int i = tid; i < 1024; i += 256) {
            int t = i >> 9, rc = i & 511, r = rc >> 2, c = rc & 3;
            const __half* g = (t ? g_k1 : g_k0) +
                ((size_t)bh * SPAD + n0 + r) * 128 + e0 + c * 8;
            cp16(kbase + st * KSTG + t * CTILE + (r * CP + c * 8) * 2, g);
        }
        cp_commit();
    };

    float acc[4][4][4];
    #pragma unroll
    for (int mt = 0; mt < 4; ++mt)
        #pragma unroll
        for (int nt = 0; nt < 4; ++nt)
            #pragma unroll
            for (int i = 0; i < 4; ++i) acc[mt][nt][i] = 0.f;

    load_k(0, 0);
    const float scl = 0.08838834764831845f;  // 1/sqrt(128)

    for (int cc = 0; cc < 32; ++cc) {
        if (cc + 1 < 32) load_k((cc + 1) & 1, cc + 1);
        if (cc + 1 < 32) cp_wait<1>(); else cp_wait<0>();
        __syncthreads();

        const u32 st = kbase + (cc & 1) * KSTG;
        const int e0 = (cc & 3) * 32;
        const int PA[3] = {0, 0, 1};
        const int PB[3] = {0, 1, 0};
        #pragma unroll
        for (int l = 0; l < 3; ++l) {
            u32 aoff = sbase + PA[l] * QTILEF;
            u32 bbase = st + PB[l] * CTILE;
            #pragma unroll
            for (int k = 0; k < 2; ++k) {
                const int k0 = k * 16;
                u32 bfrag[4][2];
                u32 brow = bbase + ((wc * 32 + (l15 & 7)) * CP + k0 + ((l15 >> 3) * 8)) * 2;
                #pragma unroll
                for (int nt = 0; nt < 4; ++nt)
                    ldmx2(bfrag[nt][0], bfrag[nt][1], brow + (nt * 8 * CP) * 2);
                u32 arow = aoff + ((wr * 64 + l15) * QP2 + e0 + k0 + ((lane >> 4) * 8)) * 2;
                #pragma unroll
                for (int mt = 0; mt < 4; ++mt) {
                    u32 a0, a1, a2, a3;
                    ldmx4(a0, a1, a2, a3, arow + (mt * 16 * QP2) * 2);
                    #pragma unroll
                    for (int nt = 0; nt < 4; ++nt)
                        mma16816(acc[mt][nt], a0, a1, a2, a3, bfrag[nt][0], bfrag[nt][1]);
                }
            }
        }
        __syncthreads();

        if ((cc & 3) == 3) {
            // epilogue for n-tile cc>>2 via the just-consumed k stage
            const int n0 = (cc >> 2) * 128;
            float* stg = (float*)(sm + 2 * QTILEF + (cc & 1) * KSTG);  // [128][33]
            #pragma unroll
            for (int g = 0; g < 4; ++g) {
                if (wc == g) {
                    int row = wr * 64 + (lane >> 2);
                    int col = (lane & 3) * 2;
                    #pragma unroll
                    for (int mt = 0; mt < 4; ++mt)
                        #pragma unroll
                        for (int nt = 0; nt < 4; ++nt) {
                            float* c = acc[mt][nt];
                            int rr = row + mt * 16, cc2 = col + nt * 8;
                            stg[rr * 33 + cc2]           = c[0];
                            stg[rr * 33 + cc2 + 1]       = c[1];
                            stg[(rr + 8) * 33 + cc2]     = c[2];
                            stg[(rr + 8) * 33 + cc2 + 1] = c[3];
                        }
                }
                __syncthreads();
                #pragma unroll
                for (int it = 0; it < 16; ++it) {
                    int i = tid + it * 256;
                    int r = i >> 5, c = i & 31;
                    int s = m0 + r;
                    if (s < Ss)
                        atten[((size_t)bh * Ss + s) * Ss + n0 + g * 32 + c] = stg[r * 33 + c] * scl;
                }
                __syncthreads();
            }
            #pragma unroll
            for (int mt = 0; mt < 4; ++mt)
                #pragma unroll
                for (int nt = 0; nt < 4; ++nt)
                    #pragma unroll
                    for (int i = 0; i < 4; ++i) acc[mt][nt][i] = 0.f;
        }
    }
}

// =================================================================
// Kernel 2b: last column t=1024 of atten (fp32 GEMV). Grid (72, 9), 128 thr.
// =================================================================
__global__ __launch_bounds__(128) void lastcol_kernel(float* __restrict__ atten)
{
    __shared__ float kv[128];
    const int bh = blockIdx.x, rblk = blockIdx.y;
    const int tid = threadIdx.x, wid = tid >> 5, lane = tid & 31;

    {
        size_t kb = ((size_t)bh * SPAD + 1024) * 128 + tid;
        kv[tid] = __half2float(g_k0[kb]) + __half2float(g_k1[kb]);
    }
    __syncthreads();

    const float scl = 0.08838834764831845f;
    for (int r = 0; r < 32; ++r) {
        int s = rblk * 128 + wid * 32 + r;
        if (s >= Ss) break;
        size_t qb = ((size_t)bh * SPAD + s) * 128 + lane * 4;
        float acc = 0.f;
        #pragma unroll
        for (int j = 0; j < 4; ++j) {
            float qv = __half2float(g_q0[qb + j]) + __half2float(g_q1[qb + j]);
            acc += qv * kv[lane * 4 + j];
        }
        #pragma unroll
        for (int o = 16; o; o >>= 1) acc += __shfl_xor_sync(0xffffffffu, acc, o);
        if (lane == 0)
            atten[((size_t)bh * Ss + s) * Ss + 1024] = acc * scl;
    }
}

// =================================================================
// Kernel 3: softmax per row; writes fp32 atten AND single fp16 P0.
// =================================================================
__global__ __launch_bounds__(128) void softmax_kernel(float* __restrict__ atten)
{
    __shared__ float buf[Ss];
    __shared__ float redm[4], reds[4];
    const int tid = threadIdx.x, wid = tid >> 5, lid = tid & 31;
    const int row = blockIdx.x;
    const int bh = row / Ss, s = row % Ss;
    float* p = atten + (size_t)row * Ss;

    float m = -3.0e38f;
    for (int c = tid; c < Ss; c += 128) { float v = p[c]; buf[c] = v; m = fmaxf(m, v); }
    #pragma unroll
    for (int o = 16; o; o >>= 1) m = fmaxf(m, __shfl_xor_sync(0xffffffffu, m, o));
    if (lid == 0) redm[wid] = m;
    __syncthreads();
    m = fmaxf(fmaxf(redm[0], redm[1]), fmaxf(redm[2], redm[3]));

    float sum = 0.f;
    for (int c = tid; c < Ss; c += 128) { float e = __expf(buf[c] - m); buf[c] = e; sum += e; }
    #pragma unroll
    for (int o = 16; o; o >>= 1) sum += __shfl_xor_sync(0xffffffffu, sum, o);
    if (lid == 0) reds[wid] = sum;
    __syncthreads();
    float inv = 1.f / (reds[0] + reds[1] + reds[2] + reds[3]);

    __half* prow = g_p0 + ((size_t)bh * SPAD + s) * SPAD;
    for (int c2 = tid; c2 * 2 < Ss; c2 += 128) {
        int c = c2 * 2;
        float pr0 = buf[c] * inv;
        p[c] = pr0;
        if (c + 1 < Ss) {
            float pr1 = buf[c + 1] * inv;
            p[c + 1] = pr1;
            *(__half2*)&prow[c] = __floats2half2_rn(pr0, pr1);
        } else {
            prow[c] = __float2half_rn(pr0);
        }
    }
}

// =================================================================
// Kernel 4: AV. fp16 P0 x V0 (1 product), 33 k32 chunks (covers 1056>=1025).
// Grid (9, 72). 2 CTAs/SM.
// =================================================================
__global__ __launch_bounds__(256, 2) void av_kernel()
{
    extern __shared__ __align__(16) unsigned char sm[];
    const u32 sbase = s2u(sm);
    const int tid = threadIdx.x, wid = tid >> 5, lane = tid & 31;
    const int m0 = blockIdx.x * 128;
    const int bh = blockIdx.y;
    const int b = bh / Hh, h = bh % Hh;
    const int wr = wid >> 2, wc = wid & 3;
    const int l15 = lane & 15;
    const int STG = CTILE + VTILE32;   // 18,944
    const int NCK = 33;

    auto load_chunk = [&](int st, int ck) {
        const int t0 = ck * 32;
        for (int i = tid; i < 1024; i += 256) {
            if (i < 512) {
                int r = i >> 2, c = i & 3;
                const __half* g = g_p0 + ((size_t)bh * SPAD + m0 + r) * SPAD + t0 + c * 8;
                cp16(sbase + st * STG + (r * CP + c * 8) * 2, g);
            } else {
                int j = i - 512;
                int r = j >> 4, c = j & 15;
                const __half* g = g_v0 + ((size_t)bh * SPAD + t0 + r) * 128 + c * 8;
                cp16(sbase + st * STG + CTILE + (r * VP + c * 8) * 2, g);
            }
        }
        cp_commit();
    };

    float acc[4][4][4];
    #pragma unroll
    for (int mt = 0; mt < 4; ++mt)
        #pragma unroll
        for (int nt = 0; nt < 4; ++nt)
            #pragma unroll
            for (int i = 0; i < 4; ++i) acc[mt][nt][i] = 0.f;

    load_chunk(0, 0);
    for (int ck = 0; ck < NCK; ++ck) {
        if (ck + 1 < NCK) load_chunk((ck + 1) & 1, ck + 1);
        if (ck + 1 < NCK) cp_wait<1>(); else cp_wait<0>();
        __syncthreads();

        const u32 st = sbase + (ck & 1) * STG;
        const u32 vbase = st + CTILE;
        #pragma unroll
        for (int k = 0; k < 2; ++k) {
            const int k0 = k * 16;
            u32 bfrag[4][2];
            u32 brow = vbase + ((k0 + l15) * VP) * 2;
            #pragma unroll
            for (int nt = 0; nt < 4; ++nt)
                ldmx2t(bfrag[nt][0], bfrag[nt][1], brow + (wc * 32 + nt * 8) * 2);
            u32 arow = st + ((wr * 64 + l15) * CP + k0 + ((lane >> 4) * 8)) * 2;
            #pragma unroll
            for (int mt = 0; mt < 4; ++mt) {
                u32 a0, a1, a2, a3;
                ldmx4(a0, a1, a2, a3, arow + (mt * 16 * CP) * 2);
                #pragma unroll
                for (int nt = 0; nt < 4; ++nt)
                    mma16816(acc[mt][nt], a0, a1, a2, a3, bfrag[nt][0], bfrag[nt][1]);
            }
        }
        __syncthreads();
    }

    float* stage = (float*)sm;   // [128][130] = 66,560 B
    {
        int row = wr * 64 + (lane >> 2);
        int col = wc * 32 + (lane & 3) * 2;
        #pragma unroll
        for (int mt = 0; mt < 4; ++mt)
            #pragma unroll
            for (int nt = 0; nt < 4; ++nt) {
                float* c = acc[mt][nt];
                int rr = row + mt * 16, cc = col + nt * 8;
                *(float2*)&stage[rr * 130 + cc]       = make_float2(c[0], c[1]);
                *(float2*)&stage[(rr + 8) * 130 + cc] = make_float2(c[2], c[3]);
            }
    }
    __syncthreads();
    for (int idx = tid; idx < 128 * 16; idx += 256) {
        int rr = idx >> 4, c8 = (idx & 15) * 8;
        int s = m0 + rr;
        if (s < Ss) {
            union { uint4 u; __half hh[8]; } h0;
            #pragma unroll
            for (int c = 0; c < 8; ++c)
                h0.hh[c] = __float2half_rn(stage[rr * 130 + c8 + c]);
            *(uint4*)&g_h0[((size_t)b * Ss + s) * HE + h * Ee + c8] = h0.u;
        }
    }
}

// =================================================================
// Kernel 5: outproj via fp16 HMMA (1 product), 18 k64 chunks. 2 CTAs/SM.
// =================================================================
__global__ __launch_bounds__(256, 2) void outproj_kernel(
    const float* __restrict__ bias, float* __restrict__ out)
{
    extern __shared__ __align__(16) unsigned char sm[];
    const u32 sbase = s2u(sm);
    const int tid = threadIdx.x, wid = tid >> 5, lane = tid & 31;
    const int row0 = blockIdx.x * 64;
    const int wr = wid >> 2, wc = wid & 3;
    const int l15 = lane & 15;
    const int STG = OATILE + OBTILE;   // 27,648

    auto load_chunk = [&](int st, int ck) {
        const int k0g = ck * 64;
        for (int i = tid; i < 1536; i += 256) {
            if (i < 512) {
                int r = i >> 3, c = i & 7;
                const __half* g = g_h0 + (size_t)(row0 + r) * HE + k0g + c * 8;
                cp16(sbase + st * STG + (r * OAP + c * 8) * 2, g);
            } else {
                int j = i - 512;
                int r = j >> 3, c = j & 7;
                const __half* g = g_w0 + (size_t)r * HE + k0g + c * 8;
                cp16(sbase + st * STG + OATILE + (r * OAP + c * 8) * 2, g);
            }
        }
        cp_commit();
    };

    float acc[2][4][4];
    #pragma unroll
    for (int mt = 0; mt < 2; ++mt)
        #pragma unroll
        for (int nt = 0; nt < 4; ++nt)
            #pragma unroll
            for (int i = 0; i < 4; ++i) acc[mt][nt][i] = 0.f;

    load_chunk(0, 0);
    for (int ck = 0; ck < 18; ++ck) {
        if (ck + 1 < 18) load_chunk((ck + 1) & 1, ck + 1);
        if (ck + 1 < 18) cp_wait<1>(); else cp_wait<0>();
        __syncthreads();

        const u32 st = sbase + (ck & 1) * STG;
        const u32 bbase = st + OATILE;
        #pragma unroll
        for (int k = 0; k < 4; ++k) {
            const int k0 = k * 16;
            u32 bfrag[4][2];
            u32 brow = bbase + ((wc * 32 + (l15 & 7)) * OAP + k0 + ((l15 >> 3) * 8)) * 2;
            #pragma unroll
            for (int nt = 0; nt < 4; ++nt)
                ldmx2(bfrag[nt][0], bfrag[nt][1], brow + (nt * 8 * OAP) * 2);
            u32 arow = st + ((wr * 32 + l15) * OAP + k0 + ((lane >> 4) * 8)) * 2;
            #pragma unroll
            for (int mt = 0; mt < 2; ++mt) {
                u32 a0, a1, a2, a3;
                ldmx4(a0, a1, a2, a3, arow + (mt * 16 * OAP) * 2);
                #pragma unroll
                for (int nt = 0; nt < 4; ++nt)
                    mma16816(acc[mt][nt], a0, a1, a2, a3, bfrag[nt][0], bfrag[nt][1]);
            }
        }
        __syncthreads();
    }

    float* stage = (float*)sm;   // [64][129] = 33,024 B
    {
        int row = wr * 32 + (lane >> 2);
        int col = wc * 32 + (lane & 3) * 2;
        #pragma unroll
        for (int mt = 0; mt < 2; ++mt)
            #pragma unroll
            for (int nt = 0; nt < 4; ++nt) {
                float* c = acc[mt][nt];
                int rr = row + mt * 16, cc = col + nt * 8;
                stage[rr * 129 + cc]           = c[0];
                stage[rr * 129 + cc + 1]       = c[1];
                stage[(rr + 8) * 129 + cc]     = c[2];
                stage[(rr + 8) * 129 + cc + 1] = c[3];
            }
    }
    __syncthreads();
    for (int idx = tid; idx < 128 * 64; idx += 256) {
        int e = idx >> 6, rr = idx & 63;
        int rg = row0 + rr;
        if (rg < Bb * Ss) {
            int b = rg / Ss, s = rg % Ss;
            out[((size_t)b * Ee + e) * Ss + s] = stage[rr * 129 + e] + bias[e];
        }
    }
}

// =================================================================
extern "C" void kernel_launch(void* const* d_in, const int* in_sizes, int n_in,
                              void* d_out, int out_size)
{
    const float* x    = (const float*)d_in[0];
    const float* Qw   = (const float*)d_in[1];
    const float* Kw   = (const float*)d_in[2];
    const float* Vw   = (const float*)d_in[3];
    const float* Wm   = (const float*)d_in[4];
    const float* bias = (const float*)d_in[5];

    float* out   = (float*)d_out;                    // [B,E,S]
    float* atten = out + (size_t)Bb * Ee * Ss;       // [B,H,S,S]

    const int smemP = 2 * (2 * CTILE + 2 * VTILE32); // 75,776
    const int smemS = 2 * QTILEF + 2 * 2 * CTILE;    // 110,592
    const int smemA = 128 * 130 * 4;                 // 66,560
    const int smemO = 2 * (OATILE + OBTILE);         // 55,296

    cudaFuncSetAttribute(proj_kernel,    cudaFuncAttributeMaxDynamicSharedMemorySize, smemP);
    cudaFuncSetAttribute(scores_kernel,  cudaFuncAttributeMaxDynamicSharedMemorySize, smemS);
    cudaFuncSetAttribute(av_kernel,      cudaFuncAttributeMaxDynamicSharedMemorySize, smemA);
    cudaFuncSetAttribute(outproj_kernel, cudaFuncAttributeMaxDynamicSharedMemorySize, smemO);

    wprep_kernel<<<576, 256>>>(Wm);
    qkvprep_kernel<<<1728, 256>>>(Qw, Kw, Vw);
    xprep_kernel<<<dim3(17, Bb), 256>>>(x);
    proj_kernel<<<dim3(9, Bb, 27), 256, smemP>>>();
    scores_kernel<<<dim3(9, Bb * Hh), 256, smemS>>>(atten);
    lastcol_kernel<<<dim3(Bb * Hh, 9), 128>>>(atten);
    softmax_kernel<<<Bb * Hh * Ss, 128>>>(atten);
    av_kernel<<<dim3(9, Bb * Hh), 256, smemA>>>();
    outproj_kernel<<<130, 256, smemO>>>(bias, out);
}

// round 15
// speedup vs baseline: 1.0711x; 1.0711x over previous
#include <cuda_runtime.h>
#include <cuda_fp16.h>

#define Bb 8
#define Hh 9
#define Ee 128
#define Ss 1025
#define SPAD 1152   // padded sequence (rows/cols >=1025 stay zero-initialized)
#define HE 1152
#define ROWP 8320   // padded out-proj row count (65*128)
#define CP 40       // fp16 pitch for [128 x 32] k-chunk tiles
#define CTILE 10240 // 128*40*2 bytes
#define VP 136      // fp16 pitch for [32 x 128] B-trans chunk tiles
#define VTILE32 8704 // 32*136*2 bytes
#define OAP 72      // outproj pitch for k64 tiles
#define OATILE 9216  // 64*72*2
#define OBTILE 18432 // 128*72*2

typedef unsigned long long ull;
typedef unsigned int u32;

// ---------------- scratch (zero-initialized BSS; padding never written) ------
__device__ __half g_x0[Bb * SPAD * 128], g_x1[Bb * SPAD * 128];
__device__ __half g_wq0[Hh * Ee * Ee], g_wq1[Hh * Ee * Ee];
__device__ __half g_wk0[Hh * Ee * Ee], g_wk1[Hh * Ee * Ee];
__device__ __half g_wv0[Hh * Ee * Ee], g_wv1[Hh * Ee * Ee];
__device__ __half g_q0[72 * SPAD * 128], g_q1[72 * SPAD * 128];
__device__ __half g_k0[72 * SPAD * 128], g_k1[72 * SPAD * 128];
__device__ __half g_v0[72 * SPAD * 128];
__device__ __half g_p0[(size_t)72 * SPAD * SPAD];
__device__ __half g_h0[ROWP * HE];
__device__ __half g_w0[Ee * HE];

// ---------------- async copy / mma helpers ----------------
__device__ __forceinline__ u32 s2u(const void* p) {
    u32 a;
    asm("{ .reg .u64 t; cvta.to.shared.u64 t, %1; cvt.u32.u64 %0, t; }" : "=r"(a) : "l"(p));
    return a;
}
__device__ __forceinline__ void cp16(u32 smem, const void* g) {
    asm volatile("cp.async.cg.shared.global [%0], [%1], 16;" :: "r"(smem), "l"(g));
}
__device__ __forceinline__ void cp_commit() { asm volatile("cp.async.commit_group;" ::: "memory"); }
template <int N> __device__ __forceinline__ void cp_wait() {
    asm volatile("cp.async.wait_group %0;" :: "n"(N) : "memory");
}
__device__ __forceinline__ void ldmx4(u32& a0, u32& a1, u32& a2, u32& a3, u32 addr) {
    asm volatile("ldmatrix.sync.aligned.m8n8.x4.shared.b16 {%0,%1,%2,%3}, [%4];"
                 : "=r"(a0), "=r"(a1), "=r"(a2), "=r"(a3) : "r"(addr));
}
__device__ __forceinline__ void ldmx2(u32& b0, u32& b1, u32 addr) {
    asm volatile("ldmatrix.sync.aligned.m8n8.x2.shared.b16 {%0,%1}, [%2];"
                 : "=r"(b0), "=r"(b1) : "r"(addr));
}
__device__ __forceinline__ void ldmx2t(u32& b0, u32& b1, u32 addr) {
    asm volatile("ldmatrix.sync.aligned.m8n8.x2.trans.shared.b16 {%0,%1}, [%2];"
                 : "=r"(b0), "=r"(b1) : "r"(addr));
}
__device__ __forceinline__ void mma16816(float* c, u32 a0, u32 a1, u32 a2, u32 a3,
                                         u32 b0, u32 b1) {
    asm volatile("mma.sync.aligned.m16n8k16.row.col.f32.f16.f16.f32 "
                 "{%0,%1,%2,%3}, {%4,%5,%6,%7}, {%8,%9}, {%0,%1,%2,%3};"
                 : "+f"(c[0]), "+f"(c[1]), "+f"(c[2]), "+f"(c[3])
                 : "r"(a0), "r"(a1), "r"(a2), "r"(a3), "r"(b0), "r"(b1));
}
__device__ __forceinline__ void hsplit2(float x, __half& a, __half& b) {
    a = __float2half_rn(x);
    b = __float2half_rn(x - __half2float(a));
}

// =================================================================
// Kernel 0a: W -> fp16 (single level)
// =================================================================
__global__ __launch_bounds__(256) void wprep_kernel(const float* __restrict__ Wm)
{
    int idx = blockIdx.x * 256 + threadIdx.x;
    if (idx < Ee * HE)
        g_w0[idx] = __float2half_rn(Wm[idx]);
}

// =================================================================
// Kernel 0b: split Q/K/V weight matrices into fp16 levels
// =================================================================
__global__ __launch_bounds__(256) void qkvprep_kernel(
    const float* __restrict__ Qw, const float* __restrict__ Kw,
    const float* __restrict__ Vw)
{
    int idx = blockIdx.x * 256 + threadIdx.x;
    const int N = Hh * Ee * Ee;
    if (idx < 3 * N) {
        int z = idx / N, j = idx % N;
        const float* src = (z == 0) ? Qw : (z == 1) ? Kw : Vw;
        __half* d0 = (z == 0) ? g_wq0 : (z == 1) ? g_wk0 : g_wv0;
        __half* d1 = (z == 0) ? g_wq1 : (z == 1) ? g_wk1 : g_wv1;
        __half a, b;
        hsplit2(src[j], a, b);
        d0[j] = a;
        d1[j] = b;
    }
}

// =================================================================
// Kernel 0c: transpose x [B,E,S] -> xt splits [b][s][e] fp16 x2
// =================================================================
__global__ __launch_bounds__(256) void xprep_kernel(const float* __restrict__ x)
{
    __shared__ float ts[128 * 65];
    const int tid = threadIdx.x;
    const int s0 = blockIdx.x * 64;
    const int b = blockIdx.y;

    #pragma unroll
    for (int it = 0; it < 32; ++it) {
        int idx = tid + it * 256;
        int e = idx >> 6, sl = idx & 63;
        int s = s0 + sl;
        ts[e * 65 + sl] = (s < Ss) ? x[((size_t)b * Ee + e) * Ss + s] : 0.f;
    }
    __syncthreads();
    #pragma unroll
    for (int it = 0; it < 32; ++it) {
        int idx = tid + it * 256;
        int sl = idx >> 7, e = idx & 127;
        int s = s0 + sl;
        if (s < Ss) {
            __half a, bb;
            hsplit2(ts[e * 65 + sl], a, bb);
            size_t o = ((size_t)b * SPAD + s) * 128 + e;
            g_x0[o] = a;
            g_x1[o] = bb;
        }
    }
}

// =================================================================
// Kernel 1: projections via fp16 HMMA (3 products), 4 k32 chunks.
// Grid (9, 8, 27). 2 CTAs/SM. q/k get split2 output; v single fp16.
// =================================================================
__global__ __launch_bounds__(256, 2) void proj_kernel()
{
    extern __shared__ __align__(16) unsigned char sm[];
    const u32 sbase = s2u(sm);
    const int tid = threadIdx.x, wid = tid >> 5, lane = tid & 31;
    const int m0 = blockIdx.x * 128;
    const int b = blockIdx.y;
    const int zt = blockIdx.z % 3, h = blockIdx.z / 3;
    const int wr = wid >> 2, wc = wid & 3;
    const int l15 = lane & 15;
    const int STG = 2 * CTILE + 2 * VTILE32;   // 37,888

    const __half* w0 = (zt == 0) ? g_wq0 : (zt == 1) ? g_wk0 : g_wv0;
    const __half* w1 = (zt == 0) ? g_wq1 : (zt == 1) ? g_wk1 : g_wv1;

    auto load_chunk = [&](int st, int ck) {
        const int e0 = ck * 32;
        for (int i = tid; i < 2048; i += 256) {
            if (i < 1024) {
                int t = i >> 9, rc = i & 511, r = rc >> 2, c = rc & 3;
                const __half* g = (t ? g_x1 : g_x0) +
                    ((size_t)b * SPAD + m0 + r) * 128 + e0 + c * 8;
                cp16(sbase + st * STG + t * CTILE + (r * CP + c * 8) * 2, g);
            } else {
                int j = i - 1024;
                int t = j >> 9, rc = j & 511, r = rc >> 4, c = rc & 15;
                const __half* g = (t ? w1 : w0) + ((size_t)h * 128 + e0 + r) * 128 + c * 8;
                cp16(sbase + st * STG + 2 * CTILE + t * VTILE32 + (r * VP + c * 8) * 2, g);
            }
        }
        cp_commit();
    };

    float acc[4][4][4];
    #pragma unroll
    for (int mt = 0; mt < 4; ++mt)
        #pragma unroll
        for (int nt = 0; nt < 4; ++nt)
            #pragma unroll
            for (int i = 0; i < 4; ++i) acc[mt][nt][i] = 0.f;

    load_chunk(0, 0);
    for (int ck = 0; ck < 4; ++ck) {
        if (ck + 1 < 4) load_chunk((ck + 1) & 1, ck + 1);
        if (ck + 1 < 4) cp_wait<1>(); else cp_wait<0>();
        __syncthreads();

        const u32 st = sbase + (ck & 1) * STG;
        const int PA[3] = {0, 0, 1};
        const int PB[3] = {0, 1, 0};
        #pragma unroll
        for (int l = 0; l < 3; ++l) {
            u32 abase = st + PA[l] * CTILE;
            u32 vbase = st + 2 * CTILE + PB[l] * VTILE32;
            #pragma unroll
            for (int k = 0; k < 2; ++k) {
                const int k0 = k * 16;
                u32 bfrag[4][2];
                u32 brow = vbase + ((k0 + l15) * VP) * 2;
                #pragma unroll
                for (int nt = 0; nt < 4; ++nt)
                    ldmx2t(bfrag[nt][0], bfrag[nt][1], brow + (wc * 32 + nt * 8) * 2);
                u32 arow = abase + ((wr * 64 + l15) * CP + k0 + ((lane >> 4) * 8)) * 2;
                #pragma unroll
                for (int mt = 0; mt < 4; ++mt) {
                    u32 a0, a1, a2, a3;
                    ldmx4(a0, a1, a2, a3, arow + (mt * 16 * CP) * 2);
                    #pragma unroll
                    for (int nt = 0; nt < 4; ++nt)
                        mma16816(acc[mt][nt], a0, a1, a2, a3, bfrag[nt][0], bfrag[nt][1]);
                }
            }
        }
        __syncthreads();
    }

    // epilogue: regs -> stage -> q/k fp16 splits (v: single level)
    float* stage = (float*)sm;   // [128][130]
    {
        int row = wr * 64 + (lane >> 2);
        int col = wc * 32 + (lane & 3) * 2;
        #pragma unroll
        for (int mt = 0; mt < 4; ++mt)
            #pragma unroll
            for (int nt = 0; nt < 4; ++nt) {
                float* c = acc[mt][nt];
                int rr = row + mt * 16, cc = col + nt * 8;
                *(float2*)&stage[rr * 130 + cc]       = make_float2(c[0], c[1]);
                *(float2*)&stage[(rr + 8) * 130 + cc] = make_float2(c[2], c[3]);
            }
    }
    __syncthreads();
    __half* d0 = (zt == 0) ? g_q0 : (zt == 1) ? g_k0 : g_v0;
    __half* d1 = (zt == 0) ? g_q1 : g_k1;   // valid only when zt < 2
    const int bh = b * Hh + h;
    for (int idx = tid; idx < 128 * 16; idx += 256) {
        int rr = idx >> 4, c8 = (idx & 15) * 8;
        int s = m0 + rr;
        if (s < Ss) {
            size_t base = ((size_t)bh * SPAD + s) * 128 + c8;
            union { uint4 u; __half hh[8]; } h0, h1;
            if (zt < 2) {
                #pragma unroll
                for (int c = 0; c < 8; ++c)
                    hsplit2(stage[rr * 130 + c8 + c], h0.hh[c], h1.hh[c]);
                *(uint4*)&d0[base] = h0.u;
                *(uint4*)&d1[base] = h1.u;
            } else {
                #pragma unroll
                for (int c = 0; c < 8; ++c)
                    h0.hh[c] = __float2half_rn(stage[rr * 130 + c8 + c]);
                *(uint4*)&d0[base] = h0.u;
            }
        }
    }
}

// =================================================================
// Kernel 2: scores. fp16 GEMM, 2-way split (3 products), 4 k32 chunks,
// double-buffered. Grid (72, 72): 9 m-tiles x 8 n-tiles (col 1024 via
// lastcol). 2 CTAs/SM.
// =================================================================
__global__ __launch_bounds__(256, 2) void scores_kernel(float* __restrict__ atten)
{
    extern __shared__ __align__(16) unsigned char sm[];
    const u32 sbase = s2u(sm);
    const int tid = threadIdx.x, wid = tid >> 5, lane = tid & 31;
    const int m0 = (blockIdx.x >> 3) * 128, n0r = (blockIdx.x & 7) * 128;
    const int bh = blockIdx.y;
    const int wr = wid >> 2, wc = wid & 3;
    const int l15 = lane & 15;
    const int STG = 4 * CTILE;

    auto load_chunk = [&](int st, int kc) {
        const int e0 = kc * 32;
        for (int i = tid; i < 2048; i += 256) {
            int t = i >> 9, rc = i & 511, r = rc >> 2, c = rc & 3;
            const __half* src = (t == 0) ? g_q0 : (t == 1) ? g_q1 : (t == 2) ? g_k0 : g_k1;
            int row0 = (t < 2) ? m0 : n0r;
            cp16(sbase + st * STG + t * CTILE + (r * CP + c * 8) * 2,
                 src + ((size_t)bh * SPAD + row0 + r) * 128 + e0 + c * 8);
        }
        cp_commit();
    };

    float acc[4][4][4];
    #pragma unroll
    for (int mt = 0; mt < 4; ++mt)
        #pragma unroll
        for (int nt = 0; nt < 4; ++nt)
            #pragma unroll
            for (int i = 0; i < 4; ++i) acc[mt][nt][i] = 0.f;

    load_chunk(0, 0);
    for (int kc = 0; kc < 4; ++kc) {
        if (kc + 1 < 4) load_chunk((kc + 1) & 1, kc + 1);
        if (kc + 1 < 4) cp_wait<1>(); else cp_wait<0>();
        __syncthreads();
        const u32 st = sbase + (kc & 1) * STG;
        const int PA[3] = {0, 0, 1};
        const int PB[3] = {0, 1, 0};
        #pragma unroll
        for (int l = 0; l < 3; ++l) {
            u32 abase = st + PA[l] * CTILE;
            u32 bbase = st + (2 + PB[l]) * CTILE;
            #pragma unroll
            for (int k = 0; k < 2; ++k) {
                const int k0 = k * 16;
                u32 bfrag[4][2];
                u32 brow = bbase + ((wc * 32 + (l15 & 7)) * CP + k0 + ((l15 >> 3) * 8)) * 2;
                #pragma unroll
                for (int nt = 0; nt < 4; ++nt)
                    ldmx2(bfrag[nt][0], bfrag[nt][1], brow + (nt * 8 * CP) * 2);
                u32 arow = abase + ((wr * 64 + l15) * CP + k0 + ((lane >> 4) * 8)) * 2;
                #pragma unroll
                for (int mt = 0; mt < 4; ++mt) {
                    u32 a0, a1, a2, a3;
                    ldmx4(a0, a1, a2, a3, arow + (mt * 16 * CP) * 2);
                    #pragma unroll
                    for (int nt = 0; nt < 4; ++nt)
                        mma16816(acc[mt][nt], a0, a1, a2, a3, bfrag[nt][0], bfrag[nt][1]);
                }
            }
        }
        __syncthreads();
    }

    float* stage = (float*)sm;   // [128][130]
    {
        int row = wr * 64 + (lane >> 2);
        int col = wc * 32 + (lane & 3) * 2;
        #pragma unroll
        for (int mt = 0; mt < 4; ++mt)
            #pragma unroll
            for (int nt = 0; nt < 4; ++nt) {
                float* c = acc[mt][nt];
                int rr = row + mt * 16, cc = col + nt * 8;
                *(float2*)&stage[rr * 130 + cc]       = make_float2(c[0], c[1]);
                *(float2*)&stage[(rr + 8) * 130 + cc] = make_float2(c[2], c[3]);
            }
    }
    __syncthreads();
    const float scl = 0.08838834764831845f;  // 1/sqrt(128)
    for (int idx = tid; idx < 128 * 128; idx += 256) {
        int rr = idx >> 7, c = idx & 127;
        int s = m0 + rr;
        if (s < Ss)
            atten[((size_t)bh * Ss + s) * Ss + n0r + c] = stage[rr * 130 + c] * scl;
    }
}

// =================================================================
// Kernel 2b: last column t=1024 of atten (fp32 GEMV). Grid (72, 9), 128 thr.
// =================================================================
__global__ __launch_bounds__(128) void lastcol_kernel(float* __restrict__ atten)
{
    __shared__ float kv[128];
    const int bh = blockIdx.x, rblk = blockIdx.y;
    const int tid = threadIdx.x, wid = tid >> 5, lane = tid & 31;

    {
        size_t kb = ((size_t)bh * SPAD + 1024) * 128 + tid;
        kv[tid] = __half2float(g_k0[kb]) + __half2float(g_k1[kb]);
    }
    __syncthreads();

    const float scl = 0.08838834764831845f;
    for (int r = 0; r < 32; ++r) {
        int s = rblk * 128 + wid * 32 + r;
        if (s >= Ss) break;
        size_t qb = ((size_t)bh * SPAD + s) * 128 + lane * 4;
        float acc = 0.f;
        #pragma unroll
        for (int j = 0; j < 4; ++j) {
            float qv = __half2float(g_q0[qb + j]) + __half2float(g_q1[qb + j]);
            acc += qv * kv[lane * 4 + j];
        }
        #pragma unroll
        for (int o = 16; o; o >>= 1) acc += __shfl_xor_sync(0xffffffffu, acc, o);
        if (lane == 0)
            atten[((size_t)bh * Ss + s) * Ss + 1024] = acc * scl;
    }
}

// =================================================================
// Kernel 3: softmax per row; writes fp32 atten AND single fp16 P0.
// =================================================================
__global__ __launch_bounds__(128) void softmax_kernel(float* __restrict__ atten)
{
    __shared__ float buf[Ss];
    __shared__ float redm[4], reds[4];
    const int tid = threadIdx.x, wid = tid >> 5, lid = tid & 31;
    const int row = blockIdx.x;
    const int bh = row / Ss, s = row % Ss;
    float* p = atten + (size_t)row * Ss;

    float m = -3.0e38f;
    for (int c = tid; c < Ss; c += 128) { float v = p[c]; buf[c] = v; m = fmaxf(m, v); }
    #pragma unroll
    for (int o = 16; o; o >>= 1) m = fmaxf(m, __shfl_xor_sync(0xffffffffu, m, o));
    if (lid == 0) redm[wid] = m;
    __syncthreads();
    m = fmaxf(fmaxf(redm[0], redm[1]), fmaxf(redm[2], redm[3]));

    float sum = 0.f;
    for (int c = tid; c < Ss; c += 128) { float e = __expf(buf[c] - m); buf[c] = e; sum += e; }
    #pragma unroll
    for (int o = 16; o; o >>= 1) sum += __shfl_xor_sync(0xffffffffu, sum, o);
    if (lid == 0) reds[wid] = sum;
    __syncthreads();
    float inv = 1.f / (reds[0] + reds[1] + reds[2] + reds[3]);

    __half* prow = g_p0 + ((size_t)bh * SPAD + s) * SPAD;
    for (int c2 = tid; c2 * 2 < Ss; c2 += 128) {
        int c = c2 * 2;
        float pr0 = buf[c] * inv;
        p[c] = pr0;
        if (c + 1 < Ss) {
            float pr1 = buf[c + 1] * inv;
            p[c + 1] = pr1;
            *(__half2*)&prow[c] = __floats2half2_rn(pr0, pr1);
        } else {
            prow[c] = __float2half_rn(pr0);
        }
    }
}

// =================================================================
// Kernel 4: AV. fp16 P0 x V0 (1 product), 33 k32 chunks (covers 1056>=1025).
// Grid (9, 72). 2 CTAs/SM.
// =================================================================
__global__ __launch_bounds__(256, 2) void av_kernel()
{
    extern __shared__ __align__(16) unsigned char sm[];
    const u32 sbase = s2u(sm);
    const int tid = threadIdx.x, wid = tid >> 5, lane = tid & 31;
    const int m0 = blockIdx.x * 128;
    const int bh = blockIdx.y;
    const int b = bh / Hh, h = bh % Hh;
    const int wr = wid >> 2, wc = wid & 3;
    const int l15 = lane & 15;
    const int STG = CTILE + VTILE32;   // 18,944
    const int NCK = 33;

    auto load_chunk = [&](int st, int ck) {
        const int t0 = ck * 32;
        for (int i = tid; i < 1024; i += 256) {
            if (i < 512) {
                int r = i >> 2, c = i & 3;
                const __half* g = g_p0 + ((size_t)bh * SPAD + m0 + r) * SPAD + t0 + c * 8;
                cp16(sbase + st * STG + (r * CP + c * 8) * 2, g);
            } else {
                int j = i - 512;
                int r = j >> 4, c = j & 15;
                const __half* g = g_v0 + ((size_t)bh * SPAD + t0 + r) * 128 + c * 8;
                cp16(sbase + st * STG + CTILE + (r * VP + c * 8) * 2, g);
            }
        }
        cp_commit();
    };

    float acc[4][4][4];
    #pragma unroll
    for (int mt = 0; mt < 4; ++mt)
        #pragma unroll
        for (int nt = 0; nt < 4; ++nt)
            #pragma unroll
            for (int i = 0; i < 4; ++i) acc[mt][nt][i] = 0.f;

    load_chunk(0, 0);
    for (int ck = 0; ck < NCK; ++ck) {
        if (ck + 1 < NCK) load_chunk((ck + 1) & 1, ck + 1);
        if (ck + 1 < NCK) cp_wait<1>(); else cp_wait<0>();
        __syncthreads();

        const u32 st = sbase + (ck & 1) * STG;
        const u32 vbase = st + CTILE;
        #pragma unroll
        for (int k = 0; k < 2; ++k) {
            const int k0 = k * 16;
            u32 bfrag[4][2];
            u32 brow = vbase + ((k0 + l15) * VP) * 2;
            #pragma unroll
            for (int nt = 0; nt < 4; ++nt)
                ldmx2t(bfrag[nt][0], bfrag[nt][1], brow + (wc * 32 + nt * 8) * 2);
            u32 arow = st + ((wr * 64 + l15) * CP + k0 + ((lane >> 4) * 8)) * 2;
            #pragma unroll
            for (int mt = 0; mt < 4; ++mt) {
                u32 a0, a1, a2, a3;
                ldmx4(a0, a1, a2, a3, arow + (mt * 16 * CP) * 2);
                #pragma unroll
                for (int nt = 0; nt < 4; ++nt)
                    mma16816(acc[mt][nt], a0, a1, a2, a3, bfrag[nt][0], bfrag[nt][1]);
            }
        }
        __syncthreads();
    }

    float* stage = (float*)sm;   // [128][130] = 66,560 B
    {
        int row = wr * 64 + (lane >> 2);
        int col = wc * 32 + (lane & 3) * 2;
        #pragma unroll
        for (int mt = 0; mt < 4; ++mt)
            #pragma unroll
            for (int nt = 0; nt < 4; ++nt) {
                float* c = acc[mt][nt];
                int rr = row + mt * 16, cc = col + nt * 8;
                *(float2*)&stage[rr * 130 + cc]       = make_float2(c[0], c[1]);
                *(float2*)&stage[(rr + 8) * 130 + cc] = make_float2(c[2], c[3]);
            }
    }
    __syncthreads();
    for (int idx = tid; idx < 128 * 16; idx += 256) {
        int rr = idx >> 4, c8 = (idx & 15) * 8;
        int s = m0 + rr;
        if (s < Ss) {
            union { uint4 u; __half hh[8]; } h0;
            #pragma unroll
            for (int c = 0; c < 8; ++c)
                h0.hh[c] = __float2half_rn(stage[rr * 130 + c8 + c]);
            *(uint4*)&g_h0[((size_t)b * Ss + s) * HE + h * Ee + c8] = h0.u;
        }
    }
}

// =================================================================
// Kernel 5: outproj via fp16 HMMA (1 product), 18 k64 chunks. 2 CTAs/SM.
// =================================================================
__global__ __launch_bounds__(256, 2) void outproj_kernel(
    const float* __restrict__ bias, float* __restrict__ out)
{
    extern __shared__ __align__(16) unsigned char sm[];
    const u32 sbase = s2u(sm);
    const int tid = threadIdx.x, wid = tid >> 5, lane = tid & 31;
    const int row0 = blockIdx.x * 64;
    const int wr = wid >> 2, wc = wid & 3;
    const int l15 = lane & 15;
    const int STG = OATILE + OBTILE;   // 27,648

    auto load_chunk = [&](int st, int ck) {
        const int k0g = ck * 64;
        for (int i = tid; i < 1536; i += 256) {
            if (i < 512) {
                int r = i >> 3, c = i & 7;
                const __half* g = g_h0 + (size_t)(row0 + r) * HE + k0g + c * 8;
                cp16(sbase + st * STG + (r * OAP + c * 8) * 2, g);
            } else {
                int j = i - 512;
                int r = j >> 3, c = j & 7;
                const __half* g = g_w0 + (size_t)r * HE + k0g + c * 8;
                cp16(sbase + st * STG + OATILE + (r * OAP + c * 8) * 2, g);
            }
        }
        cp_commit();
    };

    float acc[2][4][4];
    #pragma unroll
    for (int mt = 0; mt < 2; ++mt)
        #pragma unroll
        for (int nt = 0; nt < 4; ++nt)
            #pragma unroll
            for (int i = 0; i < 4; ++i) acc[mt][nt][i] = 0.f;

    load_chunk(0, 0);
    for (int ck = 0; ck < 18; ++ck) {
        if (ck + 1 < 18) load_chunk((ck + 1) & 1, ck + 1);
        if (ck + 1 < 18) cp_wait<1>(); else cp_wait<0>();
        __syncthreads();

        const u32 st = sbase + (ck & 1) * STG;
        const u32 bbase = st + OATILE;
        #pragma unroll
        for (int k = 0; k < 4; ++k) {
            const int k0 = k * 16;
            u32 bfrag[4][2];
            u32 brow = bbase + ((wc * 32 + (l15 & 7)) * OAP + k0 + ((l15 >> 3) * 8)) * 2;
            #pragma unroll
            for (int nt = 0; nt < 4; ++nt)
                ldmx2(bfrag[nt][0], bfrag[nt][1], brow + (nt * 8 * OAP) * 2);
            u32 arow = st + ((wr * 32 + l15) * OAP + k0 + ((lane >> 4) * 8)) * 2;
            #pragma unroll
            for (int mt = 0; mt < 2; ++mt) {
                u32 a0, a1, a2, a3;
                ldmx4(a0, a1, a2, a3, arow + (mt * 16 * OAP) * 2);
                #pragma unroll
                for (int nt = 0; nt < 4; ++nt)
                    mma16816(acc[mt][nt], a0, a1, a2, a3, bfrag[nt][0], bfrag[nt][1]);
            }
        }
        __syncthreads();
    }

    float* stage = (float*)sm;   // [64][129] = 33,024 B
    {
        int row = wr * 32 + (lane >> 2);
        int col = wc * 32 + (lane & 3) * 2;
        #pragma unroll
        for (int mt = 0; mt < 2; ++mt)
            #pragma unroll
            for (int nt = 0; nt < 4; ++nt) {
                float* c = acc[mt][nt];
                int rr = row + mt * 16, cc = col + nt * 8;
                stage[rr * 129 + cc]           = c[0];
                stage[rr * 129 + cc + 1]       = c[1];
                stage[(rr + 8) * 129 + cc]     = c[2];
                stage[(rr + 8) * 129 + cc + 1] = c[3];
            }
    }
    __syncthreads();
    for (int idx = tid; idx < 128 * 64; idx += 256) {
        int e = idx >> 6, rr = idx & 63;
        int rg = row0 + rr;
        if (rg < Bb * Ss) {
            int b = rg / Ss, s = rg % Ss;
            out[((size_t)b * Ee + e) * Ss + s] = stage[rr * 129 + e] + bias[e];
        }
    }
}

// =================================================================
extern "C" void kernel_launch(void* const* d_in, const int* in_sizes, int n_in,
                              void* d_out, int out_size)
{
    const float* x    = (const float*)d_in[0];
    const float* Qw   = (const float*)d_in[1];
    const float* Kw   = (const float*)d_in[2];
    const float* Vw   = (const float*)d_in[3];
    const float* Wm   = (const float*)d_in[4];
    const float* bias = (const float*)d_in[5];

    float* out   = (float*)d_out;                    // [B,E,S]
    float* atten = out + (size_t)Bb * Ee * Ss;       // [B,H,S,S]

    const int smemP = 2 * (2 * CTILE + 2 * VTILE32); // 75,776
    const int smemS = 2 * 4 * CTILE;                 // 81,920
    const int smemA = 128 * 130 * 4;                 // 66,560
    const int smemO = 2 * (OATILE + OBTILE);         // 55,296

    cudaFuncSetAttribute(proj_kernel,    cudaFuncAttributeMaxDynamicSharedMemorySize, smemP);
    cudaFuncSetAttribute(scores_kernel,  cudaFuncAttributeMaxDynamicSharedMemorySize, smemS);
    cudaFuncSetAttribute(av_kernel,      cudaFuncAttributeMaxDynamicSharedMemorySize, smemA);
    cudaFuncSetAttribute(outproj_kernel, cudaFuncAttributeMaxDynamicSharedMemorySize, smemO);

    wprep_kernel<<<576, 256>>>(Wm);
    qkvprep_kernel<<<1728, 256>>>(Qw, Kw, Vw);
    xprep_kernel<<<dim3(17, Bb), 256>>>(x);
    proj_kernel<<<dim3(9, Bb, 27), 256, smemP>>>();
    scores_kernel<<<dim3(72, Bb * Hh), 256, smemS>>>(atten);
    lastcol_kernel<<<dim3(Bb * Hh, 9), 128>>>(atten);
    softmax_kernel<<<Bb * Hh * Ss, 128>>>(atten);
    av_kernel<<<dim3(9, Bb * Hh), 256, smemA>>>();
    outproj_kernel<<<130, 256, smemO>>>(bias, out);
}

// round 17
// speedup vs baseline: 1.1279x; 1.0530x over previous
#include <cuda_runtime.h>
#include <cuda_fp16.h>

#define Bb 8
#define Hh 9
#define Ee 128
#define Ss 1025
#define SPAD 1152   // padded sequence (rows/cols >=1025 stay zero-initialized)
#define HE 1152
#define ROWP 8320   // padded out-proj row count (65*128)
#define CP 40       // fp16 pitch for [128 x 32] k-chunk tiles
#define CTILE 10240 // 128*40*2 bytes
#define VP 136      // fp16 pitch for [32 x 128] B-trans chunk tiles
#define VTILE32 8704 // 32*136*2 bytes
#define OAP 72      // outproj pitch for k64 tiles
#define OATILE 9216  // 64*72*2
#define OBTILE 18432 // 128*72*2

typedef unsigned long long ull;
typedef unsigned int u32;

// ---------------- scratch (zero-initialized BSS; padding never written) ------
__device__ __half g_x0[Bb * SPAD * 128], g_x1[Bb * SPAD * 128];
__device__ __half g_wq0[Hh * Ee * Ee], g_wq1[Hh * Ee * Ee];
__device__ __half g_wk0[Hh * Ee * Ee], g_wk1[Hh * Ee * Ee];
__device__ __half g_wv0[Hh * Ee * Ee];
__device__ __half g_q0[72 * SPAD * 128], g_q1[72 * SPAD * 128];
__device__ __half g_k0[72 * SPAD * 128], g_k1[72 * SPAD * 128];
__device__ __half g_v0[72 * SPAD * 128];
__device__ __half g_p0[(size_t)72 * SPAD * SPAD];
__device__ __half g_h0[ROWP * HE];
__device__ __half g_w0[Ee * HE];

// ---------------- async copy / mma helpers ----------------
__device__ __forceinline__ u32 s2u(const void* p) {
    u32 a;
    asm("{ .reg .u64 t; cvta.to.shared.u64 t, %1; cvt.u32.u64 %0, t; }" : "=r"(a) : "l"(p));
    return a;
}
__device__ __forceinline__ void cp16(u32 smem, const void* g) {
    asm volatile("cp.async.cg.shared.global [%0], [%1], 16;" :: "r"(smem), "l"(g));
}
__device__ __forceinline__ void cp_commit() { asm volatile("cp.async.commit_group;" ::: "memory"); }
template <int N> __device__ __forceinline__ void cp_wait() {
    asm volatile("cp.async.wait_group %0;" :: "n"(N) : "memory");
}
__device__ __forceinline__ void ldmx4(u32& a0, u32& a1, u32& a2, u32& a3, u32 addr) {
    asm volatile("ldmatrix.sync.aligned.m8n8.x4.shared.b16 {%0,%1,%2,%3}, [%4];"
                 : "=r"(a0), "=r"(a1), "=r"(a2), "=r"(a3) : "r"(addr));
}
__device__ __forceinline__ void ldmx2(u32& b0, u32& b1, u32 addr) {
    asm volatile("ldmatrix.sync.aligned.m8n8.x2.shared.b16 {%0,%1}, [%2];"
                 : "=r"(b0), "=r"(b1) : "r"(addr));
}
__device__ __forceinline__ void ldmx2t(u32& b0, u32& b1, u32 addr) {
    asm volatile("ldmatrix.sync.aligned.m8n8.x2.trans.shared.b16 {%0,%1}, [%2];"
                 : "=r"(b0), "=r"(b1) : "r"(addr));
}
__device__ __forceinline__ void mma16816(float* c, u32 a0, u32 a1, u32 a2, u32 a3,
                                         u32 b0, u32 b1) {
    asm volatile("mma.sync.aligned.m16n8k16.row.col.f32.f16.f16.f32 "
                 "{%0,%1,%2,%3}, {%4,%5,%6,%7}, {%8,%9}, {%0,%1,%2,%3};"
                 : "+f"(c[0]), "+f"(c[1]), "+f"(c[2]), "+f"(c[3])
                 : "r"(a0), "r"(a1), "r"(a2), "r"(a3), "r"(b0), "r"(b1));
}
__device__ __forceinline__ void hsplit2(float x, __half& a, __half& b) {
    a = __float2half_rn(x);
    b = __float2half_rn(x - __half2float(a));
}

// =================================================================
// Kernel 0: fused prep. Grid 2440: [0,576) W->fp16, [576,2304) QKV splits,
// [2304,2440) x transpose+split.
// =================================================================
__global__ __launch_bounds__(256) void prep_kernel(
    const float* __restrict__ x, const float* __restrict__ Qw,
    const float* __restrict__ Kw, const float* __restrict__ Vw,
    const float* __restrict__ Wm)
{
    __shared__ float ts[128 * 65];
    const int bx = blockIdx.x, tid = threadIdx.x;

    if (bx < 576) {
        int idx = bx * 256 + tid;
        if (idx < Ee * HE)
            g_w0[idx] = __float2half_rn(Wm[idx]);
        return;
    }
    if (bx < 2304) {
        int idx = (bx - 576) * 256 + tid;
        const int N = Hh * Ee * Ee;
        if (idx < 3 * N) {
            int z = idx / N, j = idx % N;
            const float* src = (z == 0) ? Qw : (z == 1) ? Kw : Vw;
            if (z == 2) {
                g_wv0[j] = __float2half_rn(src[j]);
            } else {
                __half a, b;
                hsplit2(src[j], a, b);
                if (z == 0) { g_wq0[j] = a; g_wq1[j] = b; }
                else        { g_wk0[j] = a; g_wk1[j] = b; }
            }
        }
        return;
    }
    // x transpose + split
    const int bx2 = bx - 2304;
    const int s0 = (bx2 % 17) * 64;
    const int b = bx2 / 17;
    #pragma unroll
    for (int it = 0; it < 32; ++it) {
        int idx = tid + it * 256;
        int e = idx >> 6, sl = idx & 63;
        int s = s0 + sl;
        ts[e * 65 + sl] = (s < Ss) ? x[((size_t)b * Ee + e) * Ss + s] : 0.f;
    }
    __syncthreads();
    #pragma unroll
    for (int it = 0; it < 32; ++it) {
        int idx = tid + it * 256;
        int sl = idx >> 7, e = idx & 127;
        int s = s0 + sl;
        if (s < Ss) {
            __half a, bb;
            hsplit2(ts[e * 65 + sl], a, bb);
            size_t o = ((size_t)b * SPAD + s) * 128 + e;
            g_x0[o] = a;
            g_x1[o] = bb;
        }
    }
}

// =================================================================
// Kernel 1: projections via fp16 HMMA, fragment-shared mainloop.
// q/k: 3 products; v: 1 product. Grid (9, 8, 27). 2 CTAs/SM.
// =================================================================
__global__ __launch_bounds__(256, 2) void proj_kernel()
{
    extern __shared__ __align__(16) unsigned char sm[];
    const u32 sbase = s2u(sm);
    const int tid = threadIdx.x, wid = tid >> 5, lane = tid & 31;
    const int m0 = blockIdx.x * 128;
    const int b = blockIdx.y;
    const int zt = blockIdx.z % 3, h = blockIdx.z / 3;
    const int wr = wid >> 2, wc = wid & 3;
    const int l15 = lane & 15;
    const int STG = 2 * CTILE + 2 * VTILE32;   // 37,888

    const __half* w0 = (zt == 0) ? g_wq0 : (zt == 1) ? g_wk0 : g_wv0;
    const __half* w1 = (zt == 0) ? g_wq1 : g_wk1;   // unused when zt==2

    auto load_chunk = [&](int st, int ck) {
        const int e0 = ck * 32;
        for (int i = tid; i < 2048; i += 256) {
            if (zt == 2 && ((i >= 512 && i < 1024) || i >= 1536)) continue;
            if (i < 1024) {
                int t = i >> 9, rc = i & 511, r = rc >> 2, c = rc & 3;
                const __half* g = (t ? g_x1 : g_x0) +
                    ((size_t)b * SPAD + m0 + r) * 128 + e0 + c * 8;
                cp16(sbase + st * STG + t * CTILE + (r * CP + c * 8) * 2, g);
            } else {
                int j = i - 1024;
                int t = j >> 9, rc = j & 511, r = rc >> 4, c = rc & 15;
                const __half* g = (t ? w1 : w0) + ((size_t)h * 128 + e0 + r) * 128 + c * 8;
                cp16(sbase + st * STG + 2 * CTILE + t * VTILE32 + (r * VP + c * 8) * 2, g);
            }
        }
        cp_commit();
    };

    float acc[4][4][4];
    #pragma unroll
    for (int mt = 0; mt < 4; ++mt)
        #pragma unroll
        for (int nt = 0; nt < 4; ++nt)
            #pragma unroll
            for (int i = 0; i < 4; ++i) acc[mt][nt][i] = 0.f;

    load_chunk(0, 0);
    for (int ck = 0; ck < 4; ++ck) {
        if (ck + 1 < 4) load_chunk((ck + 1) & 1, ck + 1);
        if (ck + 1 < 4) cp_wait<1>(); else cp_wait<0>();
        __syncthreads();

        const u32 st = sbase + (ck & 1) * STG;
        #pragma unroll
        for (int k = 0; k < 2; ++k) {
            const int k0 = k * 16;
            u32 bfrag[2][4][2];
            {
                u32 brow = st + 2 * CTILE + ((k0 + l15) * VP) * 2;
                #pragma unroll
                for (int nt = 0; nt < 4; ++nt)
                    ldmx2t(bfrag[0][nt][0], bfrag[0][nt][1], brow + (wc * 32 + nt * 8) * 2);
                if (zt < 2) {
                    u32 brow1 = brow + VTILE32;
                    #pragma unroll
                    for (int nt = 0; nt < 4; ++nt)
                        ldmx2t(bfrag[1][nt][0], bfrag[1][nt][1], brow1 + (wc * 32 + nt * 8) * 2);
                }
            }
            u32 aoff = ((wr * 64 + l15) * CP + k0 + ((lane >> 4) * 8)) * 2;
            #pragma unroll
            for (int mt = 0; mt < 4; ++mt) {
                u32 a0, a1, a2, a3;
                ldmx4(a0, a1, a2, a3, st + aoff + (mt * 16 * CP) * 2);
                #pragma unroll
                for (int nt = 0; nt < 4; ++nt)
                    mma16816(acc[mt][nt], a0, a1, a2, a3, bfrag[0][nt][0], bfrag[0][nt][1]);
                if (zt < 2) {
                    #pragma unroll
                    for (int nt = 0; nt < 4; ++nt)
                        mma16816(acc[mt][nt], a0, a1, a2, a3, bfrag[1][nt][0], bfrag[1][nt][1]);
                    ldmx4(a0, a1, a2, a3, st + CTILE + aoff + (mt * 16 * CP) * 2);
                    #pragma unroll
                    for (int nt = 0; nt < 4; ++nt)
                        mma16816(acc[mt][nt], a0, a1, a2, a3, bfrag[0][nt][0], bfrag[0][nt][1]);
                }
            }
        }
        __syncthreads();
    }

    // epilogue: regs -> stage -> q/k fp16 splits (v: single level)
    float* stage = (float*)sm;   // [128][130]
    {
        int row = wr * 64 + (lane >> 2);
        int col = wc * 32 + (lane & 3) * 2;
        #pragma unroll
        for (int mt = 0; mt < 4; ++mt)
            #pragma unroll
            for (int nt = 0; nt < 4; ++nt) {
                float* c = acc[mt][nt];
                int rr = row + mt * 16, cc = col + nt * 8;
                *(float2*)&stage[rr * 130 + cc]       = make_float2(c[0], c[1]);
                *(float2*)&stage[(rr + 8) * 130 + cc] = make_float2(c[2], c[3]);
            }
    }
    __syncthreads();
    __half* d0 = (zt == 0) ? g_q0 : (zt == 1) ? g_k0 : g_v0;
    __half* d1 = (zt == 0) ? g_q1 : g_k1;   // valid only when zt < 2
    const int bh = b * Hh + h;
    for (int idx = tid; idx < 128 * 16; idx += 256) {
        int rr = idx >> 4, c8 = (idx & 15) * 8;
        int s = m0 + rr;
        if (s < Ss) {
            size_t base = ((size_t)bh * SPAD + s) * 128 + c8;
            union { uint4 u; __half hh[8]; } h0, h1;
            if (zt < 2) {
                #pragma unroll
                for (int c = 0; c < 8; ++c)
                    hsplit2(stage[rr * 130 + c8 + c], h0.hh[c], h1.hh[c]);
                *(uint4*)&d0[base] = h0.u;
                *(uint4*)&d1[base] = h1.u;
            } else {
                #pragma unroll
                for (int c = 0; c < 8; ++c)
                    h0.hh[c] = __float2half_rn(stage[rr * 130 + c8 + c]);
                *(uint4*)&d0[base] = h0.u;
            }
        }
    }
}

// =================================================================
// Kernel 2: scores, fragment-shared. Grid (81, 72): bx<72 => 9m x 8n tiles;
// bx in [72,81) => lastcol GEMV slice (rblk = bx-72). 2 CTAs/SM.
// =================================================================
__global__ __launch_bounds__(256, 2) void scores_kernel(float* __restrict__ atten)
{
    extern __shared__ __align__(16) unsigned char sm[];
    const u32 sbase = s2u(sm);
    const int tid = threadIdx.x, wid = tid >> 5, lane = tid & 31;
    const int bh = blockIdx.y;
    const float scl = 0.08838834764831845f;  // 1/sqrt(128)

    if (blockIdx.x >= 72) {
        // ---- lastcol: atten[.., 1024] via fp32 GEMV ----
        float* kv = (float*)sm;
        if (tid < 128) {
            size_t kb = ((size_t)bh * SPAD + 1024) * 128 + tid;
            kv[tid] = __half2float(g_k0[kb]) + __half2float(g_k1[kb]);
        }
        __syncthreads();
        const int rblk = blockIdx.x - 72;
        for (int r = 0; r < 16; ++r) {
            int s = rblk * 128 + wid * 16 + r;
            if (s >= Ss) break;
            size_t qb = ((size_t)bh * SPAD + s) * 128 + lane * 4;
            float acc = 0.f;
            #pragma unroll
            for (int j = 0; j < 4; ++j) {
                float qv = __half2float(g_q0[qb + j]) + __half2float(g_q1[qb + j]);
                acc += qv * kv[lane * 4 + j];
            }
            #pragma unroll
            for (int o = 16; o; o >>= 1) acc += __shfl_xor_sync(0xffffffffu, acc, o);
            if (lane == 0)
                atten[((size_t)bh * Ss + s) * Ss + 1024] = acc * scl;
        }
        return;
    }

    const int m0 = (blockIdx.x >> 3) * 128, n0r = (blockIdx.x & 7) * 128;
    const int wr = wid >> 2, wc = wid & 3;
    const int l15 = lane & 15;
    const int STG = 4 * CTILE;

    auto load_chunk = [&](int st, int kc) {
        const int e0 = kc * 32;
        for (int i = tid; i < 2048; i += 256) {
            int t = i >> 9, rc = i & 511, r = rc >> 2, c = rc & 3;
            const __half* src = (t == 0) ? g_q0 : (t == 1) ? g_q1 : (t == 2) ? g_k0 : g_k1;
            int row0 = (t < 2) ? m0 : n0r;
            cp16(sbase + st * STG + t * CTILE + (r * CP + c * 8) * 2,
                 src + ((size_t)bh * SPAD + row0 + r) * 128 + e0 + c * 8);
        }
        cp_commit();
    };

    float acc[4][4][4];
    #pragma unroll
    for (int mt = 0; mt < 4; ++mt)
        #pragma unroll
        for (int nt = 0; nt < 4; ++nt)
            #pragma unroll
            for (int i = 0; i < 4; ++i) acc[mt][nt][i] = 0.f;

    load_chunk(0, 0);
    for (int kc = 0; kc < 4; ++kc) {
        if (kc + 1 < 4) load_chunk((kc + 1) & 1, kc + 1);
        if (kc + 1 < 4) cp_wait<1>(); else cp_wait<0>();
        __syncthreads();
        const u32 st = sbase + (kc & 1) * STG;
        #pragma unroll
        for (int k = 0; k < 2; ++k) {
            const int k0 = k * 16;
            u32 bfrag[2][4][2];
            {
                u32 brow = st + 2 * CTILE +
                    ((wc * 32 + (l15 & 7)) * CP + k0 + ((l15 >> 3) * 8)) * 2;
                #pragma unroll
                for (int nt = 0; nt < 4; ++nt)
                    ldmx2(bfrag[0][nt][0], bfrag[0][nt][1], brow + (nt * 8 * CP) * 2);
                u32 brow1 = brow + CTILE;
                #pragma unroll
                for (int nt = 0; nt < 4; ++nt)
                    ldmx2(bfrag[1][nt][0], bfrag[1][nt][1], brow1 + (nt * 8 * CP) * 2);
            }
            u32 aoff = ((wr * 64 + l15) * CP + k0 + ((lane >> 4) * 8)) * 2;
            #pragma unroll
            for (int mt = 0; mt < 4; ++mt) {
                u32 a0, a1, a2, a3;
                ldmx4(a0, a1, a2, a3, st + aoff + (mt * 16 * CP) * 2);   // q0
                #pragma unroll
                for (int nt = 0; nt < 4; ++nt)
                    mma16816(acc[mt][nt], a0, a1, a2, a3, bfrag[0][nt][0], bfrag[0][nt][1]);
                #pragma unroll
                for (int nt = 0; nt < 4; ++nt)
                    mma16816(acc[mt][nt], a0, a1, a2, a3, bfrag[1][nt][0], bfrag[1][nt][1]);
                ldmx4(a0, a1, a2, a3, st + CTILE + aoff + (mt * 16 * CP) * 2);   // q1
                #pragma unroll
                for (int nt = 0; nt < 4; ++nt)
                    mma16816(acc[mt][nt], a0, a1, a2, a3, bfrag[0][nt][0], bfrag[0][nt][1]);
            }
        }
        __syncthreads();
    }

    float* stage = (float*)sm;   // [128][130]
    {
        int row = wr * 64 + (lane >> 2);
        int col = wc * 32 + (lane & 3) * 2;
        #pragma unroll
        for (int mt = 0; mt < 4; ++mt)
            #pragma unroll
            for (int nt = 0; nt < 4; ++nt) {
                float* c = acc[mt][nt];
                int rr = row + mt * 16, cc = col + nt * 8;
                *(float2*)&stage[rr * 130 + cc]       = make_float2(c[0], c[1]);
                *(float2*)&stage[(rr + 8) * 130 + cc] = make_float2(c[2], c[3]);
            }
    }
    __syncthreads();
    for (int idx = tid; idx < 128 * 128; idx += 256) {
        int rr = idx >> 7, c = idx & 127;
        int s = m0 + rr;
        if (s < Ss)
            atten[((size_t)bh * Ss + s) * Ss + n0r + c] = stage[rr * 130 + c] * scl;
    }
}

// =================================================================
// Kernel 3: softmax per row; writes fp32 atten AND single fp16 P0.
// =================================================================
__global__ __launch_bounds__(128) void softmax_kernel(float* __restrict__ atten)
{
    __shared__ float buf[Ss];
    __shared__ float redm[4], reds[4];
    const int tid = threadIdx.x, wid = tid >> 5, lid = tid & 31;
    const int row = blockIdx.x;
    const int bh = row / Ss, s = row % Ss;
    float* p = atten + (size_t)row * Ss;

    float m = -3.0e38f;
    for (int c = tid; c < Ss; c += 128) { float v = p[c]; buf[c] = v; m = fmaxf(m, v); }
    #pragma unroll
    for (int o = 16; o; o >>= 1) m = fmaxf(m, __shfl_xor_sync(0xffffffffu, m, o));
    if (lid == 0) redm[wid] = m;
    __syncthreads();
    m = fmaxf(fmaxf(redm[0], redm[1]), fmaxf(redm[2], redm[3]));

    float sum = 0.f;
    for (int c = tid; c < Ss; c += 128) { float e = __expf(buf[c] - m); buf[c] = e; sum += e; }
    #pragma unroll
    for (int o = 16; o; o >>= 1) sum += __shfl_xor_sync(0xffffffffu, sum, o);
    if (lid == 0) reds[wid] = sum;
    __syncthreads();
    float inv = 1.f / (reds[0] + reds[1] + reds[2] + reds[3]);

    __half* prow = g_p0 + ((size_t)bh * SPAD + s) * SPAD;
    for (int c2 = tid; c2 * 2 < Ss; c2 += 128) {
        int c = c2 * 2;
        float pr0 = buf[c] * inv;
        p[c] = pr0;
        if (c + 1 < Ss) {
            float pr1 = buf[c + 1] * inv;
            p[c + 1] = pr1;
            *(__half2*)&prow[c] = __floats2half2_rn(pr0, pr1);
        } else {
            prow[c] = __float2half_rn(pr0);
        }
    }
}

// =================================================================
// Kernel 4: AV. fp16 P0 x V0 (1 product), 33 k32 chunks. Grid (9, 72).
// =================================================================
__global__ __launch_bounds__(256, 2) void av_kernel()
{
    extern __shared__ __align__(16) unsigned char sm[];
    const u32 sbase = s2u(sm);
    const int tid = threadIdx.x, wid = tid >> 5, lane = tid & 31;
    const int m0 = blockIdx.x * 128;
    const int bh = blockIdx.y;
    const int b = bh / Hh, h = bh % Hh;
    const int wr = wid >> 2, wc = wid & 3;
    const int l15 = lane & 15;
    const int STG = CTILE + VTILE32;   // 18,944
    const int NCK = 33;

    auto load_chunk = [&](int st, int ck) {
        const int t0 = ck * 32;
        for (int i = tid; i < 1024; i += 256) {
            if (i < 512) {
                int r = i >> 2, c = i & 3;
                const __half* g = g_p0 + ((size_t)bh * SPAD + m0 + r) * SPAD + t0 + c * 8;
                cp16(sbase + st * STG + (r * CP + c * 8) * 2, g);
            } else {
                int j = i - 512;
                int r = j >> 4, c = j & 15;
                const __half* g = g_v0 + ((size_t)bh * SPAD + t0 + r) * 128 + c * 8;
                cp16(sbase + st * STG + CTILE + (r * VP + c * 8) * 2, g);
            }
        }
        cp_commit();
    };

    float acc[4][4][4];
    #pragma unroll
    for (int mt = 0; mt < 4; ++mt)
        #pragma unroll
        for (int nt = 0; nt < 4; ++nt)
            #pragma unroll
            for (int i = 0; i < 4; ++i) acc[mt][nt][i] = 0.f;

    load_chunk(0, 0);
    for (int ck = 0; ck < NCK; ++ck) {
        if (ck + 1 < NCK) load_chunk((ck + 1) & 1, ck + 1);
        if (ck + 1 < NCK) cp_wait<1>(); else cp_wait<0>();
        __syncthreads();

        const u32 st = sbase + (ck & 1) * STG;
        const u32 vbase = st + CTILE;
        #pragma unroll
        for (int k = 0; k < 2; ++k) {
            const int k0 = k * 16;
            u32 bfrag[4][2];
            u32 brow = vbase + ((k0 + l15) * VP) * 2;
            #pragma unroll
            for (int nt = 0; nt < 4; ++nt)
                ldmx2t(bfrag[nt][0], bfrag[nt][1], brow + (wc * 32 + nt * 8) * 2);
            u32 arow = st + ((wr * 64 + l15) * CP + k0 + ((lane >> 4) * 8)) * 2;
            #pragma unroll
            for (int mt = 0; mt < 4; ++mt) {
                u32 a0, a1, a2, a3;
                ldmx4(a0, a1, a2, a3, arow + (mt * 16 * CP) * 2);
                #pragma unroll
                for (int nt = 0; nt < 4; ++nt)
                    mma16816(acc[mt][nt], a0, a1, a2, a3, bfrag[nt][0], bfrag[nt][1]);
            }
        }
        __syncthreads();
    }

    float* stage = (float*)sm;   // [128][130] = 66,560 B
    {
        int row = wr * 64 + (lane >> 2);
        int col = wc * 32 + (lane & 3) * 2;
        #pragma unroll
        for (int mt = 0; mt < 4; ++mt)
            #pragma unroll
            for (int nt = 0; nt < 4; ++nt) {
                float* c = acc[mt][nt];
                int rr = row + mt * 16, cc = col + nt * 8;
                *(float2*)&stage[rr * 130 + cc]       = make_float2(c[0], c[1]);
                *(float2*)&stage[(rr + 8) * 130 + cc] = make_float2(c[2], c[3]);
            }
    }
    __syncthreads();
    for (int idx = tid; idx < 128 * 16; idx += 256) {
        int rr = idx >> 4, c8 = (idx & 15) * 8;
        int s = m0 + rr;
        if (s < Ss) {
            union { uint4 u; __half hh[8]; } h0;
            #pragma unroll
            for (int c = 0; c < 8; ++c)
                h0.hh[c] = __float2half_rn(stage[rr * 130 + c8 + c]);
            *(uint4*)&g_h0[((size_t)b * Ss + s) * HE + h * Ee + c8] = h0.u;
        }
    }
}

// =================================================================
// Kernel 5: outproj via fp16 HMMA (1 product), 18 k64 chunks. 2 CTAs/SM.
// =================================================================
__global__ __launch_bounds__(256, 2) void outproj_kernel(
    const float* __restrict__ bias, float* __restrict__ out)
{
    extern __shared__ __align__(16) unsigned char sm[];
    const u32 sbase = s2u(sm);
    const int tid = threadIdx.x, wid = tid >> 5, lane = tid & 31;
    const int row0 = blockIdx.x * 64;
    const int wr = wid >> 2, wc = wid & 3;
    const int l15 = lane & 15;
    const int STG = OATILE + OBTILE;   // 27,648

    auto load_chunk = [&](int st, int ck) {
        const int k0g = ck * 64;
        for (int i = tid; i < 1536; i += 256) {
            if (i < 512) {
                int r = i >> 3, c = i & 7;
                const __half* g = g_h0 + (size_t)(row0 + r) * HE + k0g + c * 8;
                cp16(sbase + st * STG + (r * OAP + c * 8) * 2, g);
            } else {
                int j = i - 512;
                int r = j >> 3, c = j & 7;
                const __half* g = g_w0 + (size_t)r * HE + k0g + c * 8;
                cp16(sbase + st * STG + OATILE + (r * OAP + c * 8) * 2, g);
            }
        }
        cp_commit();
    };

    float acc[2][4][4];
    #pragma unroll
    for (int mt = 0; mt < 2; ++mt)
        #pragma unroll
        for (int nt = 0; nt < 4; ++nt)
            #pragma unroll
            for (int i = 0; i < 4; ++i) acc[mt][nt][i] = 0.f;

    load_chunk(0, 0);
    for (int ck = 0; ck < 18; ++ck) {
        if (ck + 1 < 18) load_chunk((ck + 1) & 1, ck + 1);
        if (ck + 1 < 18) cp_wait<1>(); else cp_wait<0>();
        __syncthreads();

        const u32 st = sbase + (ck & 1) * STG;
        const u32 bbase = st + OATILE;
        #pragma unroll
        for (int k = 0; k < 4; ++k) {
            const int k0 = k * 16;
            u32 bfrag[4][2];
            u32 brow = bbase + ((wc * 32 + (l15 & 7)) * OAP + k0 + ((l15 >> 3) * 8)) * 2;
            #pragma unroll
            for (int nt = 0; nt < 4; ++nt)
                ldmx2(bfrag[nt][0], bfrag[nt][1], brow + (nt * 8 * OAP) * 2);
            u32 arow = st + ((wr * 32 + l15) * OAP + k0 + ((lane >> 4) * 8)) * 2;
            #pragma unroll
            for (int mt = 0; mt < 2; ++mt) {
                u32 a0, a1, a2, a3;
                ldmx4(a0, a1, a2, a3, arow + (mt * 16 * OAP) * 2);
                #pragma unroll
                for (int nt = 0; nt < 4; ++nt)
                    mma16816(acc[mt][nt], a0, a1, a2, a3, bfrag[nt][0], bfrag[nt][1]);
            }
        }
        __syncthreads();
    }

    float* stage = (float*)sm;   // [64][129] = 33,024 B
    {
        int row = wr * 32 + (lane >> 2);
        int col = wc * 32 + (lane & 3) * 2;
        #pragma unroll
        for (int mt = 0; mt < 2; ++mt)
            #pragma unroll
            for (int nt = 0; nt < 4; ++nt) {
                float* c = acc[mt][nt];
                int rr = row + mt * 16, cc = col + nt * 8;
                stage[rr * 129 + cc]           = c[0];
                stage[rr * 129 + cc + 1]       = c[1];
                stage[(rr + 8) * 129 + cc]     = c[2];
                stage[(rr + 8) * 129 + cc + 1] = c[3];
            }
    }
    __syncthreads();
    for (int idx = tid; idx < 128 * 64; idx += 256) {
        int e = idx >> 6, rr = idx & 63;
        int rg = row0 + rr;
        if (rg < Bb * Ss) {
            int b = rg / Ss, s = rg % Ss;
            out[((size_t)b * Ee + e) * Ss + s] = stage[rr * 129 + e] + bias[e];
        }
    }
}

// =================================================================
extern "C" void kernel_launch(void* const* d_in, const int* in_sizes, int n_in,
                              void* d_out, int out_size)
{
    const float* x    = (const float*)d_in[0];
    const float* Qw   = (const float*)d_in[1];
    const float* Kw   = (const float*)d_in[2];
    const float* Vw   = (const float*)d_in[3];
    const float* Wm   = (const float*)d_in[4];
    const float* bias = (const float*)d_in[5];

    float* out   = (float*)d_out;                    // [B,E,S]
    float* atten = out + (size_t)Bb * Ee * Ss;       // [B,H,S,S]

    const int smemP = 2 * (2 * CTILE + 2 * VTILE32); // 75,776
    const int smemS = 2 * 4 * CTILE;                 // 81,920
    const int smemA = 128 * 130 * 4;                 // 66,560
    const int smemO = 2 * (OATILE + OBTILE);         // 55,296

    cudaFuncSetAttribute(proj_kernel,    cudaFuncAttributeMaxDynamicSharedMemorySize, smemP);
    cudaFuncSetAttribute(scores_kernel,  cudaFuncAttributeMaxDynamicSharedMemorySize, smemS);
    cudaFuncSetAttribute(av_kernel,      cudaFuncAttributeMaxDynamicSharedMemorySize, smemA);
    cudaFuncSetAttribute(outproj_kernel, cudaFuncAttributeMaxDynamicSharedMemorySize, smemO);

    prep_kernel<<<2440, 256>>>(x, Qw, Kw, Vw, Wm);
    proj_kernel<<<dim3(9, Bb, 27), 256, smemP>>>();
    scores_kernel<<<dim3(81, Bb * Hh), 256, smemS>>>(atten);
    softmax_kernel<<<Bb * Hh * Ss, 128>>>(atten);
    av_kernel<<<dim3(9, Bb * Hh), 256, smemA>>>();
    outproj_kernel<<<130, 256, smemO>>>(bias, out);
}